// round 2
// baseline (speedup 1.0000x reference)
#include <cuda_runtime.h>
#include <cstdint>

#define BATCH    1024
#define IN_BITS  4096
#define NUM_LUTS 16384
#define KBITS    6
#define NGROUPS  (BATCH / 32)          // 32 groups of 32 batches
#define LTILE    256                   // luts per block
#define BC       8                     // batch-groups per block (256 batches)

// Scratch (no cudaMalloc allowed): transposed bit-pack + narrowed connections.
// g_bits[g][p] : bit j = (x_bits[(g*32+j), p] > 0.5)
__device__ uint32_t g_bits[NGROUPS][IN_BITS];        // 512 KB
__device__ uint16_t g_conn[NUM_LUTS * KBITS];        // 196 KB

// ---------------------------------------------------------------------------
// Kernel A: pack bits, transposed across the batch dimension.
// ---------------------------------------------------------------------------
__global__ void __launch_bounds__(256) pack_kernel(const float* __restrict__ x) {
    const int g     = blockIdx.y;
    const int p0    = blockIdx.x * 1024 + threadIdx.x * 4;
    const float4* xp = (const float4*)(x + (size_t)(g * 32) * IN_BITS + p0);

    uint32_t a0 = 0, a1 = 0, a2 = 0, a3 = 0;
#pragma unroll
    for (int j = 0; j < 32; ++j) {
        float4 v = xp[(size_t)j * (IN_BITS / 4)];
        a0 |= (v.x > 0.5f ? 1u : 0u) << j;
        a1 |= (v.y > 0.5f ? 1u : 0u) << j;
        a2 |= (v.z > 0.5f ? 1u : 0u) << j;
        a3 |= (v.w > 0.5f ? 1u : 0u) << j;
    }
    uint4 o; o.x = a0; o.y = a1; o.z = a2; o.w = a3;
    *(uint4*)&g_bits[g][p0] = o;
}

// ---------------------------------------------------------------------------
// Kernel B: narrow conn_idx -> uint16. JAX without x64 silently emits int32
// even though the reference names int64; sniff the layout device-side.
// If int64 (little-endian), odd 32-bit words are the high halves == 0 for all
// entries (values < 4096). 32 random int32 samples all being 0 is impossible.
// ---------------------------------------------------------------------------
__global__ void __launch_bounds__(256) conn_kernel(const int* __restrict__ conn32) {
    // dtype sniff (identical result in every thread; 128B broadcast read)
    uint32_t acc = 0;
#pragma unroll
    for (int s = 1; s < 64; s += 2) acc |= (uint32_t)conn32[s];
    const bool is_i64 = (acc == 0u);

    int i = blockIdx.x * 256 + threadIdx.x;
    if (i < NUM_LUTS * KBITS) {
        int v = is_i64 ? conn32[2 * i] : conn32[i];
        g_conn[i] = (uint16_t)v;
    }
}

// ---------------------------------------------------------------------------
// Kernel C: main LUT evaluation.
// grid = (NUM_LUTS/LTILE, NGROUPS/BC), block = 256 (thread = one LUT).
// Shared: bit column (16 KB) + 256 table rows padded to 65 floats (66.5 KB).
// ---------------------------------------------------------------------------
__global__ void __launch_bounds__(256, 2) lut_kernel(const float* __restrict__ table,
                                                     float* __restrict__ out) {
    extern __shared__ uint32_t smem[];
    uint32_t* sbits = smem;                         // IN_BITS words (16 KB)
    float*    stab  = (float*)(smem + IN_BITS);     // LTILE * 65 floats

    const int t       = threadIdx.x;
    const int lutbase = blockIdx.x * LTILE;
    const int g0      = blockIdx.y * BC;
    const int lut     = lutbase + t;

    // Load this block's 256 table rows into shared (coalesced; stride 65 pad).
    {
        const float* gt = table + (size_t)lutbase * 64;
#pragma unroll
        for (int i = t; i < LTILE * 64; i += 256) {
            int l = i >> 6, c = i & 63;
            stab[l * 65 + c] = gt[i];
        }
    }

    const uint16_t* cp = &g_conn[(size_t)lut * KBITS];
    const int c0 = cp[0], c1 = cp[1], c2 = cp[2], c3 = cp[3], c4 = cp[4], c5 = cp[5];
    const float* trow = stab + t * 65;

    for (int g = g0; g < g0 + BC; ++g) {
        __syncthreads();
        {
            const uint4* src = (const uint4*)g_bits[g];
            uint4* dst = (uint4*)sbits;
#pragma unroll
            for (int i = t; i < IN_BITS / 4; i += 256) dst[i] = src[i];
        }
        __syncthreads();

        const uint32_t w0 = sbits[c0], w1 = sbits[c1], w2 = sbits[c2];
        const uint32_t w3 = sbits[c3], w4 = sbits[c4], w5 = sbits[c5];

        float* op = out + (size_t)(g * 32) * NUM_LUTS + lut;
#pragma unroll
        for (int j = 0; j < 32; ++j) {
            unsigned idx = (((w0 >> j) & 1u) << 5) | (((w1 >> j) & 1u) << 4)
                         | (((w2 >> j) & 1u) << 3) | (((w3 >> j) & 1u) << 2)
                         | (((w4 >> j) & 1u) << 1) |  ((w5 >> j) & 1u);
            float v = trow[idx];
            float r = __fdividef(1.0f, 1.0f + __expf(-v));
            op[(size_t)j * NUM_LUTS] = r;
        }
    }
}

// ---------------------------------------------------------------------------
extern "C" void kernel_launch(void* const* d_in, const int* in_sizes, int n_in,
                              void* d_out, int out_size) {
    const float* x    = (const float*)d_in[0];   // (1024, 4096) f32
    const float* tab  = (const float*)d_in[1];   // (16384, 64) f32
    const int*   conn = (const int*)d_in[2];     // (16384, 6) i32 (or i64 -> sniffed)
    float*       out  = (float*)d_out;           // (1024, 16384) f32

    static const int SMEM = (IN_BITS + LTILE * 65) * 4;  // 82944 B
    cudaFuncSetAttribute(lut_kernel, cudaFuncAttributeMaxDynamicSharedMemorySize, SMEM);

    dim3 gridA(IN_BITS / 1024, NGROUPS);
    pack_kernel<<<gridA, 256>>>(x);

    conn_kernel<<<(NUM_LUTS * KBITS + 255) / 256, 256>>>(conn);

    dim3 gridC(NUM_LUTS / LTILE, NGROUPS / BC);
    lut_kernel<<<gridC, 256, SMEM>>>(tab, out);
}

// round 3
// speedup vs baseline: 1.3167x; 1.3167x over previous
#include <cuda_runtime.h>
#include <cstdint>

#define BATCH    1024
#define IN_BITS  4096
#define NUM_LUTS 16384
#define KBITS    6
#define NGROUPS  (BATCH / 32)          // 32 groups of 32 batches
#define LTILE    256                   // luts per block
#define BC       8                     // batch-groups per block (256 batches)

// Scratch (no cudaMalloc): transposed bit-pack, narrowed conn, sigmoided table.
__device__ uint32_t g_bits[NGROUPS][IN_BITS];        // 512 KB
__device__ uint16_t g_conn[NUM_LUTS * KBITS];        // 196 KB
__device__ float    g_sig[NUM_LUTS * 64];            // 4 MB

// ---------------------------------------------------------------------------
// Kernel A: transposed bit-pack. 1 column/thread, 32 rows, coalesced.
// grid = (IN_BITS/256, NGROUPS) = 512 blocks.
// ---------------------------------------------------------------------------
__global__ void __launch_bounds__(256) pack_kernel(const float* __restrict__ x) {
    const int g = blockIdx.y;
    const int p = blockIdx.x * 256 + threadIdx.x;
    const float* xp = x + (size_t)(g * 32) * IN_BITS + p;
    uint32_t a = 0;
#pragma unroll
    for (int j = 0; j < 32; ++j)
        a |= (__ldg(xp + (size_t)j * IN_BITS) > 0.5f ? 1u : 0u) << j;
    g_bits[g][p] = a;
}

// ---------------------------------------------------------------------------
// Kernel B: conn -> uint16 with int32/int64 layout sniff (JAX w/o x64 emits
// int32 despite the reference's int64 annotation; if truly int64 LE, every
// odd word is a zero high-half since values < 4096).
// ---------------------------------------------------------------------------
__global__ void __launch_bounds__(256) conn_kernel(const int* __restrict__ conn32) {
    uint32_t acc = 0;
#pragma unroll
    for (int s = 1; s < 64; s += 2) acc |= (uint32_t)conn32[s];
    const bool is_i64 = (acc == 0u);

    int i = blockIdx.x * 256 + threadIdx.x;
    if (i < NUM_LUTS * KBITS) {
        int v = is_i64 ? conn32[2 * i] : conn32[i];
        g_conn[i] = (uint16_t)v;
    }
}

// ---------------------------------------------------------------------------
// Kernel C: pre-apply sigmoid to the whole table (1M entries, 16x fewer
// sigmoid evals than doing it per output). float4 in/out, fully coalesced.
// ---------------------------------------------------------------------------
__global__ void __launch_bounds__(256) sig_kernel(const float* __restrict__ table) {
    int i = blockIdx.x * 256 + threadIdx.x;   // float4 index
    float4 v = ((const float4*)table)[i];
    float4 r;
    r.x = __fdividef(1.0f, 1.0f + __expf(-v.x));
    r.y = __fdividef(1.0f, 1.0f + __expf(-v.y));
    r.z = __fdividef(1.0f, 1.0f + __expf(-v.z));
    r.w = __fdividef(1.0f, 1.0f + __expf(-v.w));
    ((float4*)g_sig)[i] = r;
}

// ---------------------------------------------------------------------------
// Kernel D: main LUT evaluation — now pure idx-build + LDS + store.
// grid = (NUM_LUTS/LTILE, NGROUPS/BC), block = 256 (thread = one LUT).
// Shared: bit column (16 KB) + 256 sigmoided rows padded to 65 (66.5 KB).
// Paired-j: one shift of each word serves outputs j and j+16.
// ---------------------------------------------------------------------------
__global__ void __launch_bounds__(256, 2) lut_kernel(float* __restrict__ out) {
    extern __shared__ uint32_t smem[];
    uint32_t* sbits = smem;                         // IN_BITS words
    float*    stab  = (float*)(smem + IN_BITS);     // LTILE * 65 floats

    const int t       = threadIdx.x;
    const int lutbase = blockIdx.x * LTILE;
    const int g0      = blockIdx.y * BC;
    const int lut     = lutbase + t;

    {
        const float* gt = g_sig + (size_t)lutbase * 64;
#pragma unroll
        for (int i = t; i < LTILE * 64; i += 256) {
            int l = i >> 6, c = i & 63;
            stab[l * 65 + c] = gt[i];
        }
    }

    const uint16_t* cp = &g_conn[(size_t)lut * KBITS];
    const int c0 = cp[0], c1 = cp[1], c2 = cp[2], c3 = cp[3], c4 = cp[4], c5 = cp[5];
    const float* trow = stab + t * 65;

    for (int g = g0; g < g0 + BC; ++g) {
        __syncthreads();
        {
            const uint4* src = (const uint4*)g_bits[g];
            uint4* dst = (uint4*)sbits;
#pragma unroll
            for (int i = t; i < IN_BITS / 4; i += 256) dst[i] = src[i];
        }
        __syncthreads();

        const uint32_t w0 = sbits[c0], w1 = sbits[c1], w2 = sbits[c2];
        const uint32_t w3 = sbits[c3], w4 = sbits[c4], w5 = sbits[c5];

        float* op = out + (size_t)(g * 32) * NUM_LUTS + lut;
#pragma unroll
        for (int j = 0; j < 16; ++j) {
            // bits j and j+16 of each word -> two 6-bit indices at once
            uint32_t acc =           ((w0 >> j) & 0x00010001u);
            acc = acc * 2u + ((w1 >> j) & 0x00010001u);
            acc = acc * 2u + ((w2 >> j) & 0x00010001u);
            acc = acc * 2u + ((w3 >> j) & 0x00010001u);
            acc = acc * 2u + ((w4 >> j) & 0x00010001u);
            acc = acc * 2u + ((w5 >> j) & 0x00010001u);
            const unsigned ilo = acc & 63u;
            const unsigned ihi = acc >> 16;         // bits 16..21, already clean
            float vlo = trow[ilo];
            float vhi = trow[ihi];
            __stcs(op + (size_t)j * NUM_LUTS, vlo);
            __stcs(op + (size_t)(j + 16) * NUM_LUTS, vhi);
        }
    }
}

// ---------------------------------------------------------------------------
extern "C" void kernel_launch(void* const* d_in, const int* in_sizes, int n_in,
                              void* d_out, int out_size) {
    const float* x    = (const float*)d_in[0];   // (1024, 4096) f32
    const float* tab  = (const float*)d_in[1];   // (16384, 64) f32
    const int*   conn = (const int*)d_in[2];     // (16384, 6) i32 (sniffed)
    float*       out  = (float*)d_out;           // (1024, 16384) f32

    static const int SMEM = (IN_BITS + LTILE * 65) * 4;  // 82944 B
    cudaFuncSetAttribute(lut_kernel, cudaFuncAttributeMaxDynamicSharedMemorySize, SMEM);

    dim3 gridA(IN_BITS / 256, NGROUPS);                  // 512 blocks
    pack_kernel<<<gridA, 256>>>(x);

    conn_kernel<<<(NUM_LUTS * KBITS + 255) / 256, 256>>>(conn);

    sig_kernel<<<(NUM_LUTS * 64 / 4) / 256, 256>>>(tab); // 1024 blocks

    dim3 gridC(NUM_LUTS / LTILE, NGROUPS / BC);          // (64, 4)
    lut_kernel<<<gridC, 256, SMEM>>>(out);
}

// round 4
// speedup vs baseline: 1.3372x; 1.0156x over previous
#include <cuda_runtime.h>
#include <cstdint>

#define BATCH    1024
#define IN_BITS  4096
#define NUM_LUTS 16384
#define KBITS    6
#define NGROUPS  (BATCH / 32)          // 32 groups of 32 batches
#define LTILE    128                   // luts per block (smaller -> 4 CTAs/SM)
#define BC       8                     // batch-groups per block

// Prep grid layout (one fused kernel): [pack | sig | conn]
#define PACK_BLOCKS (IN_BITS / 256 * NGROUPS)         // 16*32 = 512
#define SIG_BLOCKS  (NUM_LUTS * 64 / 4 / 256)         // 1024
#define CONN_BLOCKS ((NUM_LUTS * KBITS + 255) / 256)  // 384

// Scratch (no cudaMalloc): transposed bit-pack, narrowed conn, sigmoided table.
__device__ uint32_t g_bits[NGROUPS][IN_BITS];        // 512 KB
__device__ uint16_t g_conn[NUM_LUTS * KBITS];        // 196 KB
__device__ float    g_sig[NUM_LUTS * 64];            // 4 MB

// ---------------------------------------------------------------------------
// Fused prep kernel: three independent jobs dispatched on blockIdx.x.
//  pack: transposed bit-pack (bit j of word = batch g*32+j at column p)
//  sig : sigmoid over the whole table (hoisted out of the hot loop, 16x fewer)
//  conn: int32/int64-sniffed narrowing to uint16 (JAX w/o x64 emits int32;
//        if truly int64 LE every odd word is a zero high-half, vals < 4096)
// ---------------------------------------------------------------------------
__global__ void __launch_bounds__(256) prep_kernel(const float* __restrict__ x,
                                                   const float* __restrict__ table,
                                                   const int* __restrict__ conn32) {
    const int b = blockIdx.x;
    if (b < PACK_BLOCKS) {
        const int g = b >> 4;                       // 16 x-blocks per group
        const int p = (b & 15) * 256 + threadIdx.x;
        const float* xp = x + (size_t)(g * 32) * IN_BITS + p;
        uint32_t a = 0;
#pragma unroll
        for (int j = 0; j < 32; ++j)
            a |= (__ldg(xp + (size_t)j * IN_BITS) > 0.5f ? 1u : 0u) << j;
        g_bits[g][p] = a;
    } else if (b < PACK_BLOCKS + SIG_BLOCKS) {
        const int i = (b - PACK_BLOCKS) * 256 + threadIdx.x;  // float4 index
        float4 v = ((const float4*)table)[i];
        float4 r;
        r.x = __fdividef(1.0f, 1.0f + __expf(-v.x));
        r.y = __fdividef(1.0f, 1.0f + __expf(-v.y));
        r.z = __fdividef(1.0f, 1.0f + __expf(-v.z));
        r.w = __fdividef(1.0f, 1.0f + __expf(-v.w));
        ((float4*)g_sig)[i] = r;
    } else {
        uint32_t acc = 0;
#pragma unroll
        for (int s = 1; s < 64; s += 2) acc |= (uint32_t)conn32[s];
        const bool is_i64 = (acc == 0u);
        const int i = (b - PACK_BLOCKS - SIG_BLOCKS) * 256 + threadIdx.x;
        if (i < NUM_LUTS * KBITS) {
            int v = is_i64 ? conn32[2 * i] : conn32[i];
            g_conn[i] = (uint16_t)v;
        }
    }
}

// ---------------------------------------------------------------------------
// Main LUT kernel. block = 256 = 128 LUTs x 2 batch-halves.
// smem = bits (16 KB) + 128 table rows padded to 65 (33.25 KB) -> 4 CTAs/SM.
// Thread owns LUT (t & 127), half h = t>>7: h=0 does j 0..7 & 16..23 (paired),
// h=1 does j 8..15 & 24..31. Paired-j: one shift serves outputs j and j+16.
// ---------------------------------------------------------------------------
__global__ void __launch_bounds__(256, 4) lut_kernel(float* __restrict__ out) {
    extern __shared__ uint32_t smem[];
    uint32_t* sbits = smem;                         // IN_BITS words (16 KB)
    float*    stab  = (float*)(smem + IN_BITS);     // LTILE * 65 floats

    const int t       = threadIdx.x;
    const int l       = t & (LTILE - 1);
    const int h       = t >> 7;                     // batch half
    const int lutbase = blockIdx.x * LTILE;
    const int g0      = blockIdx.y * BC;
    const int lut     = lutbase + l;

    // Load this block's 128 sigmoided table rows into shared (pad stride 65).
    {
        const float* gt = g_sig + (size_t)lutbase * 64;
#pragma unroll
        for (int i = t; i < LTILE * 64; i += 256) {
            int r = i >> 6, c = i & 63;
            stab[r * 65 + c] = gt[i];
        }
    }

    const uint16_t* cp = &g_conn[(size_t)lut * KBITS];
    const int c0 = cp[0], c1 = cp[1], c2 = cp[2], c3 = cp[3], c4 = cp[4], c5 = cp[5];
    const float* trow = stab + l * 65;
    const int jbase = h * 8;

    for (int g = g0; g < g0 + BC; ++g) {
        __syncthreads();
        {
            const uint4* src = (const uint4*)g_bits[g];
            uint4* dst = (uint4*)sbits;
#pragma unroll
            for (int i = t; i < IN_BITS / 4; i += 256) dst[i] = src[i];
        }
        __syncthreads();

        const uint32_t w0 = sbits[c0], w1 = sbits[c1], w2 = sbits[c2];
        const uint32_t w3 = sbits[c3], w4 = sbits[c4], w5 = sbits[c5];

        float* op = out + (size_t)(g * 32 + jbase) * NUM_LUTS + lut;
#pragma unroll
        for (int jj = 0; jj < 8; ++jj) {
            const int j = jbase + jj;
            uint32_t acc =   ((w0 >> j) & 0x00010001u);
            acc = acc * 2u + ((w1 >> j) & 0x00010001u);
            acc = acc * 2u + ((w2 >> j) & 0x00010001u);
            acc = acc * 2u + ((w3 >> j) & 0x00010001u);
            acc = acc * 2u + ((w4 >> j) & 0x00010001u);
            acc = acc * 2u + ((w5 >> j) & 0x00010001u);
            float vlo = trow[acc & 63u];
            float vhi = trow[acc >> 16];            // bits 16..21, already clean
            __stcs(op + (size_t)jj * NUM_LUTS, vlo);
            __stcs(op + (size_t)(jj + 16) * NUM_LUTS, vhi);
        }
    }
}

// ---------------------------------------------------------------------------
extern "C" void kernel_launch(void* const* d_in, const int* in_sizes, int n_in,
                              void* d_out, int out_size) {
    const float* x    = (const float*)d_in[0];   // (1024, 4096) f32
    const float* tab  = (const float*)d_in[1];   // (16384, 64) f32
    const int*   conn = (const int*)d_in[2];     // (16384, 6) i32 (sniffed)
    float*       out  = (float*)d_out;           // (1024, 16384) f32

    static const int SMEM = (IN_BITS + LTILE * 65) * 4;  // 49664 B
    cudaFuncSetAttribute(lut_kernel, cudaFuncAttributeMaxDynamicSharedMemorySize, SMEM);

    prep_kernel<<<PACK_BLOCKS + SIG_BLOCKS + CONN_BLOCKS, 256>>>(x, tab, conn);

    dim3 gridC(NUM_LUTS / LTILE, NGROUPS / BC);          // (128, 4)
    lut_kernel<<<gridC, 256, SMEM>>>(out);
}

// round 5
// speedup vs baseline: 1.6198x; 1.2113x over previous
#include <cuda_runtime.h>
#include <cstdint>

#define BATCH    1024
#define IN_BITS  4096
#define NUM_LUTS 16384
#define KBITS    6
#define NGROUPS  (BATCH / 32)          // 32 groups of 32 batches
#define LTILE    128                   // luts per block
#define BC       8                     // batch-groups per block

#define PACK_BLOCKS (IN_BITS / 256 * NGROUPS)         // 512
#define SIG_BLOCKS  (NUM_LUTS * 64 / 4 / 256)         // 1024
#define CONN_BLOCKS ((NUM_LUTS * KBITS + 255) / 256)  // 384

__device__ uint32_t g_bits[NGROUPS][IN_BITS];        // 512 KB
__device__ uint16_t g_conn[NUM_LUTS * KBITS];        // 196 KB
__device__ float    g_sig[NUM_LUTS * 64];            // 4 MB

// ---------------------------------------------------------------------------
// Fused prep: [pack | sig | conn] dispatched on blockIdx.x.
// ---------------------------------------------------------------------------
__global__ void __launch_bounds__(256) prep_kernel(const float* __restrict__ x,
                                                   const float* __restrict__ table,
                                                   const int* __restrict__ conn32) {
    const int b = blockIdx.x;
    if (b < PACK_BLOCKS) {
        const int g = b >> 4;
        const int p = (b & 15) * 256 + threadIdx.x;
        const float* xp = x + (size_t)(g * 32) * IN_BITS + p;
        uint32_t a = 0;
#pragma unroll
        for (int j = 0; j < 32; ++j)
            a |= (__ldg(xp + (size_t)j * IN_BITS) > 0.5f ? 1u : 0u) << j;
        g_bits[g][p] = a;
    } else if (b < PACK_BLOCKS + SIG_BLOCKS) {
        const int i = (b - PACK_BLOCKS) * 256 + threadIdx.x;
        float4 v = ((const float4*)table)[i];
        float4 r;
        r.x = __fdividef(1.0f, 1.0f + __expf(-v.x));
        r.y = __fdividef(1.0f, 1.0f + __expf(-v.y));
        r.z = __fdividef(1.0f, 1.0f + __expf(-v.z));
        r.w = __fdividef(1.0f, 1.0f + __expf(-v.w));
        ((float4*)g_sig)[i] = r;
    } else {
        // conn dtype sniff: JAX w/o x64 emits int32 despite int64 annotation;
        // true int64 LE would have all odd words == 0 (values < 4096).
        uint32_t acc = 0;
#pragma unroll
        for (int s = 1; s < 64; s += 2) acc |= (uint32_t)conn32[s];
        const bool is_i64 = (acc == 0u);
        const int i = (b - PACK_BLOCKS - SIG_BLOCKS) * 256 + threadIdx.x;
        if (i < NUM_LUTS * KBITS) {
            int v = is_i64 ? conn32[2 * i] : conn32[i];
            g_conn[i] = (uint16_t)v;
        }
    }
}

// ---------------------------------------------------------------------------
// cp.async helpers (16B, L2-cached straight into smem, no registers)
// ---------------------------------------------------------------------------
__device__ __forceinline__ void cp_async16(void* smem_dst, const void* gsrc) {
    uint32_t s = (uint32_t)__cvta_generic_to_shared(smem_dst);
    asm volatile("cp.async.cg.shared.global [%0], [%1], 16;\n" :: "r"(s), "l"(gsrc));
}
__device__ __forceinline__ void cp_async_commit() {
    asm volatile("cp.async.commit_group;\n" ::: "memory");
}
__device__ __forceinline__ void cp_async_wait0() {
    asm volatile("cp.async.wait_group 0;\n" ::: "memory");
}

// ---------------------------------------------------------------------------
// Main LUT kernel. block = 256 = 128 LUTs x 2 batch-halves.
// smem: two 16 KB bit buffers (double-buffered via cp.async) + table tile
// (128 rows, pad 65) = 65.3 KB -> 3 CTAs/SM, regs up to ~85 for ILP.
// One __syncthreads per g-iteration; copy latency hidden behind compute.
// ---------------------------------------------------------------------------
__global__ void __launch_bounds__(256, 3) lut_kernel(float* __restrict__ out) {
    extern __shared__ uint32_t smem[];
    uint32_t* sb0  = smem;                          // buffer 0
    uint32_t* sb1  = smem + IN_BITS;                // buffer 1
    float*    stab = (float*)(smem + 2 * IN_BITS);  // LTILE * 65 floats

    const int t       = threadIdx.x;
    const int l       = t & (LTILE - 1);
    const int h       = t >> 7;
    const int lutbase = blockIdx.x * LTILE;
    const int g0      = blockIdx.y * BC;
    const int lut     = lutbase + l;

    // Prefetch g0's bit column into buffer 0 (async, no regs burned).
    {
        const uint4* src = (const uint4*)g_bits[g0];
#pragma unroll
        for (int i = t; i < IN_BITS / 4; i += 256)
            cp_async16((uint4*)sb0 + i, src + i);
        cp_async_commit();
    }

    // Table tile load overlaps with the async bits copy.
    {
        const float* gt = g_sig + (size_t)lutbase * 64;
#pragma unroll
        for (int i = t; i < LTILE * 64; i += 256) {
            int r = i >> 6, c = i & 63;
            stab[r * 65 + c] = gt[i];
        }
    }

    const uint16_t* cp = &g_conn[(size_t)lut * KBITS];
    const int c0 = cp[0], c1 = cp[1], c2 = cp[2], c3 = cp[3], c4 = cp[4], c5 = cp[5];
    const float* trow = stab + l * 65;
    const int jbase = h * 8;

    cp_async_wait0();
    __syncthreads();

#pragma unroll 1
    for (int g = g0; g < g0 + BC; ++g) {
        uint32_t* cur = ((g - g0) & 1) ? sb1 : sb0;
        uint32_t* nxt = ((g - g0) & 1) ? sb0 : sb1;

        // Kick off next group's copy before computing this one.
        if (g + 1 < g0 + BC) {
            const uint4* src = (const uint4*)g_bits[g + 1];
#pragma unroll
            for (int i = t; i < IN_BITS / 4; i += 256)
                cp_async16((uint4*)nxt + i, src + i);
        }
        cp_async_commit();

        const uint32_t w0 = cur[c0], w1 = cur[c1], w2 = cur[c2];
        const uint32_t w3 = cur[c3], w4 = cur[c4], w5 = cur[c5];

        float* op = out + (size_t)(g * 32 + jbase) * NUM_LUTS + lut;
#pragma unroll
        for (int jj = 0; jj < 8; ++jj) {
            const int j = jbase + jj;
            uint32_t acc =   ((w0 >> j) & 0x00010001u);
            acc = acc * 2u + ((w1 >> j) & 0x00010001u);
            acc = acc * 2u + ((w2 >> j) & 0x00010001u);
            acc = acc * 2u + ((w3 >> j) & 0x00010001u);
            acc = acc * 2u + ((w4 >> j) & 0x00010001u);
            acc = acc * 2u + ((w5 >> j) & 0x00010001u);
            float vlo = trow[acc & 63u];
            float vhi = trow[acc >> 16];
            __stcs(op + (size_t)jj * NUM_LUTS, vlo);
            __stcs(op + (size_t)(jj + 16) * NUM_LUTS, vhi);
        }

        cp_async_wait0();
        __syncthreads();
    }
}

// ---------------------------------------------------------------------------
extern "C" void kernel_launch(void* const* d_in, const int* in_sizes, int n_in,
                              void* d_out, int out_size) {
    const float* x    = (const float*)d_in[0];   // (1024, 4096) f32
    const float* tab  = (const float*)d_in[1];   // (16384, 64) f32
    const int*   conn = (const int*)d_in[2];     // (16384, 6) i32 (sniffed)
    float*       out  = (float*)d_out;           // (1024, 16384) f32

    static const int SMEM = (2 * IN_BITS + LTILE * 65) * 4;  // 66048 B
    cudaFuncSetAttribute(lut_kernel, cudaFuncAttributeMaxDynamicSharedMemorySize, SMEM);

    prep_kernel<<<PACK_BLOCKS + SIG_BLOCKS + CONN_BLOCKS, 256>>>(x, tab, conn);

    dim3 gridC(NUM_LUTS / LTILE, NGROUPS / BC);          // (128, 4)
    lut_kernel<<<gridC, 256, SMEM>>>(out);
}